// round 16
// baseline (speedup 1.0000x reference)
#include <cuda_runtime.h>
#include <cuda_fp16.h>
#include <cstdint>

#define BB 4
#define SS 4096
#define DM 1024
#define DK 64
#define NSPLIT 8
#define SPLITLEN (SS / NSPLIT)   // 512 keys per split
#define NR (BB * SS)             // 16384 rows

// Scratch (device globals per allocation-guard rules)
__device__ __half g_qh[BB * SS * DK];          // fp16 Q  [token][d]
__device__ __half g_kh[BB * SS * DK];          // fp16 K  [token][d]
__device__ __half g_vt[BB * DK * SS];          // fp16 V^T [b][dv][token]
__device__ __half g_atth[BB * SS * DK];        // fp16 attention output
__device__ __half g_wh[3 * DK * DM];           // fp16 Wq|Wk|Wv  [n][d]
__device__ __half g_woh[DM * DK];              // fp16 Wo [n][v]
__device__ __half g_oph[NSPLIT][BB * SS * DK]; // fp16 unnormalized partial O
__device__ float  g_m[NSPLIT * NR];
__device__ float  g_l[NSPLIT * NR];

// ---------------------------------------------------------------------------
// helpers
// ---------------------------------------------------------------------------
__device__ __forceinline__ uint32_t pack_h2(float lo, float hi) {
    uint32_t r;
    asm("cvt.rn.f16x2.f32 %0, %1, %2;" : "=r"(r) : "f"(hi), "f"(lo));
    return r;
}

__device__ __forceinline__ void mma_f16(float* d, const uint32_t* a,
                                        uint32_t b0, uint32_t b1) {
    asm volatile(
        "mma.sync.aligned.m16n8k16.row.col.f32.f16.f16.f32 "
        "{%0,%1,%2,%3}, {%4,%5,%6,%7}, {%8,%9}, {%0,%1,%2,%3};\n"
        : "+f"(d[0]), "+f"(d[1]), "+f"(d[2]), "+f"(d[3])
        : "r"(a[0]), "r"(a[1]), "r"(a[2]), "r"(a[3]), "r"(b0), "r"(b1));
}

__device__ __forceinline__ void ldsm4(uint32_t* r, const void* p) {
    uint32_t a = (uint32_t)__cvta_generic_to_shared(p);
    asm volatile("ldmatrix.sync.aligned.m8n8.x4.shared.b16 {%0,%1,%2,%3}, [%4];"
                 : "=r"(r[0]), "=r"(r[1]), "=r"(r[2]), "=r"(r[3]) : "r"(a));
}

__device__ __forceinline__ void cp16(void* s, const void* g) {
    uint32_t sa = (uint32_t)__cvta_generic_to_shared(s);
    asm volatile("cp.async.cg.shared.global [%0], [%1], 16;" :: "r"(sa), "l"(g));
}
__device__ __forceinline__ void cp_commit() {
    asm volatile("cp.async.commit_group;");
}

// ---------------------------------------------------------------------------
// Prep: one-shot fp32 -> fp16 conversion of the weight matrices.
// ---------------------------------------------------------------------------
__global__ __launch_bounds__(128) void prep_weights_kernel(
    const float* __restrict__ Wq, const float* __restrict__ Wk,
    const float* __restrict__ Wv, const float* __restrict__ Wo)
{
    const int which = blockIdx.y;
    const float* src = (which == 0) ? Wq : (which == 1) ? Wk
                     : (which == 2) ? Wv : Wo;
    __half* dst = (which < 3) ? (g_wh + (size_t)which * DK * DM) : g_woh;

    int idx = (blockIdx.x * 128 + threadIdx.x) * 4;
    float4 v = *(const float4*)&src[idx];
    uint2 h = { pack_h2(v.x, v.y), pack_h2(v.z, v.w) };
    *(uint2*)&dst[idx] = h;
}

// ---------------------------------------------------------------------------
// QKV projection, fp16 mma + ldmatrix (unchanged from R12).
// ---------------------------------------------------------------------------
#define XSTRW 72
#define WSTRH 72
#define QKV_XBUF (64 * XSTRW)
#define QKV_SMEM (2 * QKV_XBUF * 4 + 64 * WSTRH * 2)

__global__ __launch_bounds__(128, 4) void qkv_mma_kernel(
    const float* __restrict__ q, const float* __restrict__ k,
    const float* __restrict__ v,
    const float* __restrict__ bq, const float* __restrict__ bk,
    const float* __restrict__ bv)
{
    extern __shared__ uint32_t sq[];
    float*  Xb0 = reinterpret_cast<float*>(sq);
    float*  Xb1 = Xb0 + QKV_XBUF;
    __half* Wh  = reinterpret_cast<__half*>(sq + 2 * QKV_XBUF);

    const int which = blockIdx.y;
    const float* X    = (which == 0) ? q  : (which == 1) ? k  : v;
    const float* bias = (which == 0) ? bq : (which == 1) ? bk : bv;
    const __half* Wsrc = g_wh + (size_t)which * DK * DM;

    const int m0   = blockIdx.x * 64;
    const int t    = threadIdx.x;
    const int w    = t >> 5;
    const int lane = t & 31;
    const int gi   = lane >> 2;
    const int gc   = lane & 3;

    const int srow = t >> 4;
    const int sc4  = (t & 15) << 2;
    const int hrow = t >> 3;
    const int hc8  = (t & 7) << 3;

    #pragma unroll
    for (int j = 0; j < 8; j++) {
        int row = srow + j * 8;
        cp16(&Xb0[row * XSTRW + sc4], &X[(size_t)(m0 + row) * DM + sc4]);
    }
    cp_commit();

    float acc[8][4] = {};
    const int ra = 16 * w + gi, rb = ra + 8;
    const int lrow = lane & 7;
    const int ldk  = 8 * (lane >> 3);

    for (int kc0 = 0; kc0 < 16; kc0++) {
        float* Xs = (kc0 & 1) ? Xb1 : Xb0;
        const int k0 = kc0 * 64;

        #pragma unroll
        for (int j = 0; j < 4; j++) {
            int row = hrow + j * 16;
            *reinterpret_cast<uint4*>(&Wh[row * WSTRH + hc8]) =
                *reinterpret_cast<const uint4*>(&Wsrc[(size_t)row * DM + k0 + hc8]);
        }

        if (kc0 + 1 < 16) {
            float* Xn = (kc0 & 1) ? Xb0 : Xb1;
            int k0n = k0 + 64;
            #pragma unroll
            for (int j = 0; j < 8; j++) {
                int row = srow + j * 8;
                cp16(&Xn[row * XSTRW + sc4], &X[(size_t)(m0 + row) * DM + k0n + sc4]);
            }
        }
        cp_commit();

        asm volatile("cp.async.wait_group 1;");
        __syncthreads();

        uint32_t aq[4][4];
        #pragma unroll
        for (int kc = 0; kc < 4; kc++) {
            int d = 16 * kc + 2 * gc;
            float2 xa = *(const float2*)&Xs[ra * XSTRW + d    ];
            float2 xb = *(const float2*)&Xs[rb * XSTRW + d    ];
            float2 xc = *(const float2*)&Xs[ra * XSTRW + d + 8];
            float2 xd = *(const float2*)&Xs[rb * XSTRW + d + 8];
            aq[kc][0] = pack_h2(xa.x, xa.y);
            aq[kc][1] = pack_h2(xb.x, xb.y);
            aq[kc][2] = pack_h2(xc.x, xc.y);
            aq[kc][3] = pack_h2(xd.x, xd.y);
        }

        #pragma unroll
        for (int nt = 0; nt < 8; nt++) {
            const __half* bp = Wh + (8 * nt + lrow) * WSTRH + ldk;
            uint32_t bfr[8];
            ldsm4(bfr    , bp     );
            ldsm4(bfr + 4, bp + 32);
            mma_f16(acc[nt], aq[0], bfr[0], bfr[1]);
            mma_f16(acc[nt], aq[1], bfr[2], bfr[3]);
            mma_f16(acc[nt], aq[2], bfr[4], bfr[5]);
            mma_f16(acc[nt], aq[3], bfr[6], bfr[7]);
        }
        __syncthreads();
    }

    if (which != 2) {
        __half* outh = (which == 0) ? g_qh : g_kh;
        #pragma unroll
        for (int nt = 0; nt < 8; nt++) {
            int n = 8 * nt + 2 * gc;
            float2 b2 = *(const float2*)&bias[n];
            uint32_t ha = pack_h2(acc[nt][0] + b2.x, acc[nt][1] + b2.y);
            *(uint32_t*)&outh[(size_t)(m0 + ra) * DK + n] = ha;
            uint32_t hb = pack_h2(acc[nt][2] + b2.x, acc[nt][3] + b2.y);
            *(uint32_t*)&outh[(size_t)(m0 + rb) * DK + n] = hb;
        }
    } else {
        int bidx = (m0 + ra) >> 12;
        int sa   = (m0 + ra) & (SS - 1);
        int sb   = (m0 + rb) & (SS - 1);
        __half* vt = g_vt + (size_t)bidx * DK * SS;
        #pragma unroll
        for (int nt = 0; nt < 8; nt++) {
            int n = 8 * nt + 2 * gc;
            float2 b2 = *(const float2*)&bias[n];
            vt[(size_t)(n    ) * SS + sa] = __float2half_rn(acc[nt][0] + b2.x);
            vt[(size_t)(n + 1) * SS + sa] = __float2half_rn(acc[nt][1] + b2.y);
            vt[(size_t)(n    ) * SS + sb] = __float2half_rn(acc[nt][2] + b2.x);
            vt[(size_t)(n + 1) * SS + sb] = __float2half_rn(acc[nt][3] + b2.y);
        }
    }
}

// ---------------------------------------------------------------------------
// Output projection, fp16 mma + ldmatrix (unchanged from R12).
// ---------------------------------------------------------------------------
__global__ __launch_bounds__(128, 4) void outproj_mma_kernel(const float* __restrict__ bo,
                                                             float* __restrict__ out)
{
    __shared__ __half sh[64 * WSTRH * 2];
    __half* As = sh;
    __half* Ws = sh + 64 * WSTRH;

    const int m0   = blockIdx.x * 64;
    const int n00  = blockIdx.y * 256;
    const int t    = threadIdx.x;
    const int w    = t >> 5;
    const int lane = t & 31;
    const int gi   = lane >> 2;
    const int gc   = lane & 3;

    const int hrow = t >> 3;
    const int hc8  = (t & 7) << 3;
    const int lrow = lane & 7;
    const int ldk  = 8 * (lane >> 3);

    #pragma unroll
    for (int j = 0; j < 4; j++) {
        int row = hrow + j * 16;
        *reinterpret_cast<uint4*>(&As[row * WSTRH + hc8]) =
            *reinterpret_cast<const uint4*>(&g_atth[(size_t)(m0 + row) * DK + hc8]);
    }

    const int ra = 16 * w + gi, rb = ra + 8;
    uint32_t aq[4][4];
    bool aq_done = false;

    for (int ny = 0; ny < 4; ny++) {
        const int n0 = n00 + 64 * ny;

        #pragma unroll
        for (int j = 0; j < 4; j++) {
            int row = hrow + j * 16;
            *reinterpret_cast<uint4*>(&Ws[row * WSTRH + hc8]) =
                *reinterpret_cast<const uint4*>(&g_woh[(size_t)(n0 + row) * DK + hc8]);
        }
        __syncthreads();

        if (!aq_done) {
            aq_done = true;
            #pragma unroll
            for (int kc = 0; kc < 4; kc++) {
                int d = 16 * kc + 2 * gc;
                aq[kc][0] = *(const uint32_t*)&As[ra * WSTRH + d    ];
                aq[kc][1] = *(const uint32_t*)&As[rb * WSTRH + d    ];
                aq[kc][2] = *(const uint32_t*)&As[ra * WSTRH + d + 8];
                aq[kc][3] = *(const uint32_t*)&As[rb * WSTRH + d + 8];
            }
        }

        float acc[8][4] = {};
        #pragma unroll
        for (int nt = 0; nt < 8; nt++) {
            const __half* bp = Ws + (8 * nt + lrow) * WSTRH + ldk;
            uint32_t bfr[8];
            ldsm4(bfr    , bp     );
            ldsm4(bfr + 4, bp + 32);
            mma_f16(acc[nt], aq[0], bfr[0], bfr[1]);
            mma_f16(acc[nt], aq[1], bfr[2], bfr[3]);
            mma_f16(acc[nt], aq[2], bfr[4], bfr[5]);
            mma_f16(acc[nt], aq[3], bfr[6], bfr[7]);
        }

        #pragma unroll
        for (int nt = 0; nt < 8; nt++) {
            int n = n0 + 8 * nt + 2 * gc;
            float2 b2 = *(const float2*)&bo[n];
            float2 oa = { acc[nt][0] + b2.x, acc[nt][1] + b2.y };
            *(float2*)&out[(size_t)(m0 + ra) * DM + n] = oa;
            float2 ob = { acc[nt][2] + b2.x, acc[nt][3] + b2.y };
            *(float2*)&out[(size_t)(m0 + rb) * DM + n] = ob;
        }
        __syncthreads();
    }
}

// ---------------------------------------------------------------------------
// Split-K flash attention, fp16 mma + ldmatrix (R12 synchronous staging;
// only change vs R12: fp16 partial-O epilogue).
// ---------------------------------------------------------------------------
#define HSTR 72

__global__ __launch_bounds__(128, 4) void attn_mma_kernel(const int* __restrict__ mask)
{
    __shared__ __half sh[64 * HSTR * 2];   // 18432 B
    __half* Ks  = sh;
    __half* Vts = sh + 64 * HSTR;
    __half* Qs  = sh;

    const int b     = blockIdx.y;
    const int q0    = blockIdx.x * 64;
    const int split = blockIdx.z;
    const int t     = threadIdx.x;
    const int w     = t >> 5;
    const int lane  = t & 31;
    const int gi    = lane >> 2;
    const int gc    = lane & 3;
    const float scale = 0.125f;

    const int ra = 16 * w + gi, rb = ra + 8;
    const int lrow = lane & 7;
    const int ldk  = 8 * (lane >> 3);

    const __half* qh = g_qh + ((size_t)b * SS + q0) * DK;
    #pragma unroll
    for (int j = 0; j < 4; j++) {
        int f   = t + j * 128;
        int row = f >> 3;
        int dg  = (f & 7) << 3;
        *reinterpret_cast<uint4*>(&Qs[row * HSTR + dg]) =
            *reinterpret_cast<const uint4*>(&qh[row * DK + dg]);
    }
    __syncthreads();

    uint32_t aq[4][4];
    #pragma unroll
    for (int kc = 0; kc < 4; kc++) {
        int d = 16 * kc + 2 * gc;
        aq[kc][0] = *(const uint32_t*)&Qs[ra * HSTR + d    ];
        aq[kc][1] = *(const uint32_t*)&Qs[rb * HSTR + d    ];
        aq[kc][2] = *(const uint32_t*)&Qs[ra * HSTR + d + 8];
        aq[kc][3] = *(const uint32_t*)&Qs[rb * HSTR + d + 8];
    }
    __syncthreads();

    float oacc[8][4] = {};
    float m_a = -1e30f, m_b = -1e30f, l_a = 0.0f, l_b = 0.0f;

    const int qa = q0 + ra;
    const int qb = q0 + rb;

    const __half* khb = g_kh + (size_t)b * SS * DK;
    const __half* vtb = g_vt + (size_t)b * DK * SS;
    const int2* mrow_a = (const int2*)(mask + (size_t)qa * SS);
    const int2* mrow_b = (const int2*)(mask + (size_t)qb * SS);

    const int kbeg = split * SPLITLEN;
    const int kend = kbeg + SPLITLEN;

    for (int kt = kbeg; kt < kend; kt += 64) {
        #pragma unroll
        for (int j = 0; j < 4; j++) {
            int f   = t + j * 128;
            int r   = f >> 3;
            int dg  = (f & 7) << 3;
            *reinterpret_cast<uint4*>(&Ks[r * HSTR + dg]) =
                *reinterpret_cast<const uint4*>(&khb[(size_t)(kt + r) * DK + dg]);
            *reinterpret_cast<uint4*>(&Vts[r * HSTR + dg]) =
                *reinterpret_cast<const uint4*>(&vtb[(size_t)r * SS + kt + dg]);
        }
        __syncthreads();

        float sacc[8][4];
        #pragma unroll
        for (int nt = 0; nt < 8; nt++) {
            sacc[nt][0] = 0.f; sacc[nt][1] = 0.f;
            sacc[nt][2] = 0.f; sacc[nt][3] = 0.f;
        }
        #pragma unroll
        for (int nt = 0; nt < 8; nt++) {
            const __half* bp = Ks + (8 * nt + lrow) * HSTR + ldk;
            uint32_t bfr[8];
            ldsm4(bfr    , bp     );
            ldsm4(bfr + 4, bp + 32);
            mma_f16(sacc[nt], aq[0], bfr[0], bfr[1]);
            mma_f16(sacc[nt], aq[1], bfr[2], bfr[3]);
            mma_f16(sacc[nt], aq[2], bfr[4], bfr[5]);
            mma_f16(sacc[nt], aq[3], bfr[6], bfr[7]);
        }

        const int mbase = (kt >> 1) + gc;
        #pragma unroll
        for (int nt = 0; nt < 8; nt++) {
            int2 ma = mrow_a[mbase + 4 * nt];
            int2 mb = mrow_b[mbase + 4 * nt];
            sacc[nt][0] = ma.x ? sacc[nt][0] * scale : -1e9f;
            sacc[nt][1] = ma.y ? sacc[nt][1] * scale : -1e9f;
            sacc[nt][2] = mb.x ? sacc[nt][2] * scale : -1e9f;
            sacc[nt][3] = mb.y ? sacc[nt][3] * scale : -1e9f;
        }

        float mxa = -1e30f, mxb = -1e30f;
        #pragma unroll
        for (int nt = 0; nt < 8; nt++) {
            mxa = fmaxf(mxa, fmaxf(sacc[nt][0], sacc[nt][1]));
            mxb = fmaxf(mxb, fmaxf(sacc[nt][2], sacc[nt][3]));
        }
        mxa = fmaxf(mxa, __shfl_xor_sync(0xffffffffu, mxa, 1));
        mxa = fmaxf(mxa, __shfl_xor_sync(0xffffffffu, mxa, 2));
        mxb = fmaxf(mxb, __shfl_xor_sync(0xffffffffu, mxb, 1));
        mxb = fmaxf(mxb, __shfl_xor_sync(0xffffffffu, mxb, 2));

        float mna = fmaxf(m_a, mxa);
        float mnb = fmaxf(m_b, mxb);
        float ca = __expf(m_a - mna);  m_a = mna;
        float cb = __expf(m_b - mnb);  m_b = mnb;

        uint32_t pa[4][4];
        float sla = 0.0f, slb = 0.0f;
        #pragma unroll
        for (int nt = 0; nt < 8; nt++) {
            float p0 = __expf(sacc[nt][0] - m_a);
            float p1 = __expf(sacc[nt][1] - m_a);
            float p2 = __expf(sacc[nt][2] - m_b);
            float p3 = __expf(sacc[nt][3] - m_b);
            sla += p0 + p1;
            slb += p2 + p3;
            int g = nt >> 1;
            int h = (nt & 1) << 1;
            pa[g][h    ] = pack_h2(p0, p1);
            pa[g][h + 1] = pack_h2(p2, p3);
        }
        sla += __shfl_xor_sync(0xffffffffu, sla, 1);
        sla += __shfl_xor_sync(0xffffffffu, sla, 2);
        slb += __shfl_xor_sync(0xffffffffu, slb, 1);
        slb += __shfl_xor_sync(0xffffffffu, slb, 2);
        l_a = l_a * ca + sla;
        l_b = l_b * cb + slb;

        #pragma unroll
        for (int nt = 0; nt < 8; nt++) {
            oacc[nt][0] *= ca; oacc[nt][1] *= ca;
            oacc[nt][2] *= cb; oacc[nt][3] *= cb;
        }

        #pragma unroll
        for (int nt = 0; nt < 8; nt++) {
            const __half* vp = Vts + (8 * nt + lrow) * HSTR + ldk;
            uint32_t bfr[8];
            ldsm4(bfr    , vp     );
            ldsm4(bfr + 4, vp + 32);
            mma_f16(oacc[nt], pa[0], bfr[0], bfr[1]);
            mma_f16(oacc[nt], pa[1], bfr[2], bfr[3]);
            mma_f16(oacc[nt], pa[2], bfr[4], bfr[5]);
            mma_f16(oacc[nt], pa[3], bfr[6], bfr[7]);
        }
        __syncthreads();
    }

    // ---- write unnormalized partial O (fp16) + (m, l) ----
    const size_t rowa = (size_t)b * SS + qa;
    const size_t rowb = (size_t)b * SS + qb;
    __half* op = g_oph[split];
    #pragma unroll
    for (int nt = 0; nt < 8; nt++) {
        int n = 8 * nt + 2 * gc;
        *(uint32_t*)&op[rowa * DK + n] = pack_h2(oacc[nt][0], oacc[nt][1]);
        *(uint32_t*)&op[rowb * DK + n] = pack_h2(oacc[nt][2], oacc[nt][3]);
    }
    if (gc == 0) {
        g_m[split * NR + rowa] = m_a;
        g_l[split * NR + rowa] = l_a;
        g_m[split * NR + rowb] = m_b;
        g_l[split * NR + rowb] = l_b;
    }
}

// ---------------------------------------------------------------------------
// Combine the NSPLIT fp16 partials; writes fp16 g_atth.
// ---------------------------------------------------------------------------
__global__ __launch_bounds__(128) void attn_combine_kernel()
{
    int idx = blockIdx.x * 128 + threadIdx.x;
    int row = idx >> 4;
    int c4  = (idx & 15) << 2;

    float m[NSPLIT], wgt[NSPLIT];
    float ms = -1e30f;
    #pragma unroll
    for (int s = 0; s < NSPLIT; s++) {
        m[s] = g_m[s * NR + row];
        ms = fmaxf(ms, m[s]);
    }
    float lsum = 0.0f;
    #pragma unroll
    for (int s = 0; s < NSPLIT; s++) {
        wgt[s] = __expf(m[s] - ms);
        lsum += wgt[s] * g_l[s * NR + row];
    }
    float inv = 1.0f / lsum;

    size_t off = (size_t)row * DK + c4;
    float4 o = { 0.f, 0.f, 0.f, 0.f };
    #pragma unroll
    for (int s = 0; s < NSPLIT; s++) {
        uint2 ph = *(const uint2*)&g_oph[s][off];
        float2 p01 = __half22float2(*reinterpret_cast<__half2*>(&ph.x));
        float2 p23 = __half22float2(*reinterpret_cast<__half2*>(&ph.y));
        o.x += wgt[s] * p01.x;  o.y += wgt[s] * p01.y;
        o.z += wgt[s] * p23.x;  o.w += wgt[s] * p23.y;
    }
    uint2 h = { pack_h2(o.x * inv, o.y * inv), pack_h2(o.z * inv, o.w * inv) };
    *(uint2*)&g_atth[off] = h;
}

// ---------------------------------------------------------------------------
extern "C" void kernel_launch(void* const* d_in, const int* in_sizes, int n_in,
                              void* d_out, int out_size)
{
    const float* q    = (const float*)d_in[0];
    const float* k    = (const float*)d_in[1];
    const float* v    = (const float*)d_in[2];
    const int*   mask = (const int*)  d_in[3];
    const float* Wq   = (const float*)d_in[4];
    const float* bq   = (const float*)d_in[5];
    const float* Wk   = (const float*)d_in[6];
    const float* bk   = (const float*)d_in[7];
    const float* Wv   = (const float*)d_in[8];
    const float* bv   = (const float*)d_in[9];
    const float* Wo   = (const float*)d_in[10];
    const float* bo   = (const float*)d_in[11];
    float* out = (float*)d_out;

    cudaFuncSetAttribute(qkv_mma_kernel,
                         cudaFuncAttributeMaxDynamicSharedMemorySize, QKV_SMEM);

    const int M = BB * SS;  // 16384

    prep_weights_kernel<<<dim3(DK * DM / (128 * 4), 4), 128>>>(Wq, Wk, Wv, Wo);

    qkv_mma_kernel<<<dim3(M / 64, 3), 128, QKV_SMEM>>>(q, k, v, bq, bk, bv);

    attn_mma_kernel<<<dim3(SS / 64, BB, NSPLIT), 128>>>(mask);
    attn_combine_kernel<<<(NR * 16) / 128, 128>>>();

    outproj_mma_kernel<<<dim3(M / 64, DM / 256), 128>>>(bo, out);
}